// round 2
// baseline (speedup 1.0000x reference)
#include <cuda_runtime.h>
#include <cstddef>

#define TT 1024
#define BB 16
#define CC 64
#define BIGF 1e10f
// 1/(gamma*ln2), gamma = 0.01
#define KS 144.2695040888963f
// gamma*ln2
#define GLN2 0.006931471805599453f

// Scratch (device globals: allocation-free rule)
__device__ float g_cost[(size_t)BB * TT * TT];   // 64 MB, row-major per batch
__device__ float g_nx[BB * TT];
__device__ float g_ny[BB * TT];
__device__ float g_partial[BB];

__device__ __forceinline__ float ex2f(float x) {
    float y;
    asm("ex2.approx.ftz.f32 %0, %1;" : "=f"(y) : "f"(x));
    return y;
}
__device__ __forceinline__ float lg2f(float x) {
    float y;
    asm("lg2.approx.ftz.f32 %0, %1;" : "=f"(y) : "f"(x));
    return y;
}

// ---------------------------------------------------------------------------
// Kernel 0: row norms  ||x_i||^2, ||y_j||^2  (one warp per row)
// ---------------------------------------------------------------------------
__global__ void norms_kernel(const float* __restrict__ x,
                             const float* __restrict__ y) {
    int gwarp = (blockIdx.x * blockDim.x + threadIdx.x) >> 5;
    int lane = threadIdx.x & 31;
    const int nrows = BB * TT;
    if (gwarp >= 2 * nrows) return;
    const float* src = (gwarp < nrows) ? x : y;
    float* dst = (gwarp < nrows) ? g_nx : g_ny;
    int row = (gwarp < nrows) ? gwarp : (gwarp - nrows);
    float v0 = src[(size_t)row * CC + lane];
    float v1 = src[(size_t)row * CC + 32 + lane];
    float s = v0 * v0 + v1 * v1;
    #pragma unroll
    for (int o = 16; o; o >>= 1) s += __shfl_xor_sync(0xFFFFFFFFu, s, o);
    if (lane == 0) dst[row] = s;
}

// ---------------------------------------------------------------------------
// Kernel 1: cost[b][i][j] = x2[i] + y2[j] - 2 * dot(x_i, y_j)
// 128x128 tile per CTA, 8x8 cells per thread, k split in 2 chunks of 32.
// ---------------------------------------------------------------------------
__global__ __launch_bounds__(256) void cost_kernel(const float* __restrict__ x,
                                                   const float* __restrict__ y) {
    __shared__ float xs[32][132];   // [k][i], padded: stride 132 (16B aligned rows)
    __shared__ float ys[32][132];   // [k][j]

    int b = blockIdx.z;
    int I0 = blockIdx.y * 128;
    int J0 = blockIdx.x * 128;
    int tid = threadIdx.x;
    int tx = tid & 15;        // j-block 0..15
    int ty = tid >> 4;        // i-block 0..15

    const float* xb = x + ((size_t)b * TT + I0) * CC;
    const float* yb = y + ((size_t)b * TT + J0) * CC;

    float acc[8][8];
    #pragma unroll
    for (int r = 0; r < 8; r++)
        #pragma unroll
        for (int s = 0; s < 8; s++) acc[r][s] = 0.f;

    for (int k0 = 0; k0 < CC; k0 += 32) {
        __syncthreads();
        #pragma unroll
        for (int e = 0; e < 4096; e += 256) {
            int idx = e + tid;
            int row = idx >> 5;
            int kk = idx & 31;
            xs[kk][row] = xb[(size_t)row * CC + k0 + kk];
            ys[kk][row] = yb[(size_t)row * CC + k0 + kk];
        }
        __syncthreads();
        #pragma unroll
        for (int kk = 0; kk < 32; kk++) {
            float4 xv0 = *(const float4*)&xs[kk][ty * 8];
            float4 xv1 = *(const float4*)&xs[kk][ty * 8 + 4];
            float4 yv0 = *(const float4*)&ys[kk][tx * 8];
            float4 yv1 = *(const float4*)&ys[kk][tx * 8 + 4];
            float xr[8] = {xv0.x, xv0.y, xv0.z, xv0.w, xv1.x, xv1.y, xv1.z, xv1.w};
            float yr[8] = {yv0.x, yv0.y, yv0.z, yv0.w, yv1.x, yv1.y, yv1.z, yv1.w};
            #pragma unroll
            for (int r = 0; r < 8; r++)
                #pragma unroll
                for (int s = 0; s < 8; s++)
                    acc[r][s] = fmaf(xr[r], yr[s], acc[r][s]);
        }
    }

    float x2[8], y2[8];
    #pragma unroll
    for (int r = 0; r < 8; r++) x2[r] = g_nx[b * TT + I0 + ty * 8 + r];
    #pragma unroll
    for (int s = 0; s < 8; s++) y2[s] = g_ny[b * TT + J0 + tx * 8 + s];

    float* crow = g_cost + ((size_t)b << 20) + (size_t)(I0 + ty * 8) * TT + J0 + tx * 8;
    #pragma unroll
    for (int r = 0; r < 8; r++) {
        float4 o0, o1;
        o0.x = fmaf(-2.f, acc[r][0], x2[r] + y2[0]);
        o0.y = fmaf(-2.f, acc[r][1], x2[r] + y2[1]);
        o0.z = fmaf(-2.f, acc[r][2], x2[r] + y2[2]);
        o0.w = fmaf(-2.f, acc[r][3], x2[r] + y2[3]);
        o1.x = fmaf(-2.f, acc[r][4], x2[r] + y2[4]);
        o1.y = fmaf(-2.f, acc[r][5], x2[r] + y2[5]);
        o1.z = fmaf(-2.f, acc[r][6], x2[r] + y2[6]);
        o1.w = fmaf(-2.f, acc[r][7], x2[r] + y2[7]);
        *(float4*)&crow[(size_t)r * TT] = o0;
        *(float4*)&crow[(size_t)r * TT + 4] = o1;
    }
}

// ---------------------------------------------------------------------------
// Kernel 2: soft-DTW anti-diagonal wavefront. One CTA (1024 threads) per batch.
// Triple-buffered diagonals in shared memory; one __syncthreads per diagonal.
// Thread tid owns row i = tid+1. R[i][j] with j = d - i.
// ---------------------------------------------------------------------------
__global__ __launch_bounds__(1024) void dp_kernel() {
    int b = blockIdx.x;
    int tid = threadIdx.x;
    int i = tid + 1;

    __shared__ float buf0[TT + 1], buf1[TT + 1], buf2[TT + 1];
    for (int k = tid; k < TT + 1; k += 1024) {
        buf0[k] = BIGF; buf1[k] = BIGF; buf2[k] = BIGF;
    }
    if (tid == 0) buf0[0] = 0.f;   // R[0][0]
    __syncthreads();

    float* p2 = buf0;  // diagonal d-2
    float* p1 = buf1;  // diagonal d-1
    float* pc = buf2;  // diagonal d (current write)

    // pbase[d] == cost[i-1][d-i-1]  (row-major; thread streams its own row)
    const float* pbase = g_cost + ((size_t)b << 20) + (size_t)(i - 1) * TT - i - 1;

    float cost_c = (i == 1) ? pbase[2] : 0.f;  // prefetch for d=2
    float myr = 0.f;

    for (int d = 2; d <= 2 * TT; ++d) {
        int lo = d - TT; if (lo < 1) lo = 1;
        int hi = d - 1;  if (hi > TT) hi = TT;

        // prefetch next diagonal's cost (per-lane predicated LDG)
        float cost_n = 0.f;
        if ((d < 2 * TT) && (i <= d) && (i >= d + 1 - TT)) cost_n = pbase[d + 1];

        int wbase = (tid & ~31) + 1;  // smallest i in this warp
        if ((wbase <= hi) && (wbase + 31 >= lo)) {
            float a  = p1[i - 1];   // R[i-1][j]
            float bb = p1[i];       // R[i][j-1]
            float cc = p2[i - 1];   // R[i-1][j-1]
            float m = fminf(fminf(a, bb), cc);
            float s = ex2f((m - a) * KS) + ex2f((m - bb) * KS) + ex2f((m - cc) * KS);
            float r = cost_c + m - GLN2 * lg2f(s);
            if ((i >= lo) && (i <= hi)) { pc[i] = r; myr = r; }
        }
        if (tid == 0) pc[0] = BIGF;   // keep R[0][*] = BIG on recycled buffers
        __syncthreads();
        float* t = p2; p2 = p1; p1 = pc; pc = t;
        cost_c = cost_n;
    }

    if (tid == TT - 1) g_partial[b] = myr;   // R[T][T]
}

// ---------------------------------------------------------------------------
// Kernel 3: deterministic sum of the 16 per-batch distances.
// ---------------------------------------------------------------------------
__global__ void sum_kernel(float* out) {
    if (threadIdx.x == 0) {
        float s = 0.f;
        #pragma unroll
        for (int b = 0; b < BB; b++) s += g_partial[b];
        out[0] = s;
    }
}

extern "C" void kernel_launch(void* const* d_in, const int* in_sizes, int n_in,
                              void* d_out, int out_size) {
    const float* x = (const float*)d_in[0];
    const float* y = (const float*)d_in[1];
    float* out = (float*)d_out;

    norms_kernel<<<4096, 256>>>(x, y);
    cost_kernel<<<dim3(8, 8, BB), 256>>>(x, y);
    dp_kernel<<<BB, 1024>>>();
    sum_kernel<<<1, 32>>>(out);
}